// round 9
// baseline (speedup 1.0000x reference)
#include <cuda_runtime.h>
#include <cuda_bf16.h>
#include <cstdint>

// Problem constants
#define BB   2
#define SS   2048
#define EE   1024
#define HH   16
#define HKV  4
#define DD   64
#define KVE  (HKV * DD)   // 256
#define MM   (BB * SS)    // 4096

// Scratch (allocation-free rule: __device__ globals)
__device__ float g_Q[(size_t)MM * EE];     // tf32-bit Q
__device__ float g_K[(size_t)MM * KVE];    // tf32-bit K
__device__ float g_Vt[(size_t)KVE * MM];   // tf32-bit V, TRANSPOSED [d][pos]
__device__ float g_C[(size_t)MM * EE];     // tf32-bit context
__device__ float g_xt[(size_t)MM * EE];    // tf32-bit x
__device__ float g_wqt[(size_t)EE * EE];   // tf32-bit weights
__device__ float g_wkt[(size_t)KVE * EE];
__device__ float g_wvt[(size_t)KVE * EE];
__device__ float g_wot[(size_t)EE * EE];

__device__ __forceinline__ uint32_t f2tf32(float x) {
    uint32_t u;
    asm("cvt.rna.tf32.f32 %0, %1;" : "=r"(u) : "f"(x));
    return u;
}
__device__ __forceinline__ void mma_tf32(float* c, const uint32_t* a,
                                         const uint32_t* b) {
    asm volatile(
        "mma.sync.aligned.m16n8k8.row.col.f32.tf32.tf32.f32 "
        "{%0,%1,%2,%3}, {%4,%5,%6,%7}, {%8,%9}, {%0,%1,%2,%3};"
        : "+f"(c[0]), "+f"(c[1]), "+f"(c[2]), "+f"(c[3])
        : "r"(a[0]), "r"(a[1]), "r"(a[2]), "r"(a[3]),
          "r"(b[0]), "r"(b[1]));
}
__device__ __forceinline__ void ldsm_x4(uint32_t* r, uint32_t addr) {
    asm volatile("ldmatrix.sync.aligned.m8n8.x4.shared.b16 {%0,%1,%2,%3}, [%4];"
                 : "=r"(r[0]), "=r"(r[1]), "=r"(r[2]), "=r"(r[3])
                 : "r"(addr));
}
__device__ __forceinline__ void cp16(uint32_t d, const void* s) {
    asm volatile("cp.async.cg.shared.global [%0], [%1], 16;"
                 :: "r"(d), "l"(s) : "memory");
}
__device__ __forceinline__ void cp_commit() {
    asm volatile("cp.async.commit_group;" ::: "memory");
}
__device__ __forceinline__ void cp_wait0() {
    asm volatile("cp.async.wait_group 0;" ::: "memory");
}
__device__ __forceinline__ void cp_wait1() {
    asm volatile("cp.async.wait_group 1;" ::: "memory");
}
__device__ __forceinline__ uint32_t cvta_s(const void* p) {
    return (uint32_t)__cvta_generic_to_shared(p);
}

// ===========================================================================
// Prep: convert x + all weights to tf32 bit patterns (stored as float)
// ===========================================================================
#define NX  (MM * EE)
#define NWQ (EE * EE)
#define NWK (KVE * EE)
#define NTOT (NX + NWQ + 2 * NWK + NWQ)

__global__ void __launch_bounds__(256)
prep_tf32(const float* __restrict__ x,
          const float* __restrict__ wq, const float* __restrict__ wk,
          const float* __restrict__ wv, const float* __restrict__ wo)
{
    const int nvec = NTOT / 4;
    for (int i = blockIdx.x * blockDim.x + threadIdx.x; i < nvec;
         i += gridDim.x * blockDim.x) {
        const int e = i * 4;
        const float* src;
        float* dst;
        int off;
        if (e < NX)                    { src = x;  dst = g_xt;  off = e; }
        else if (e < NX + NWQ)         { src = wq; dst = g_wqt; off = e - NX; }
        else if (e < NX + NWQ + NWK)   { src = wk; dst = g_wkt; off = e - NX - NWQ; }
        else if (e < NX + NWQ + 2*NWK) { src = wv; dst = g_wvt; off = e - NX - NWQ - NWK; }
        else                           { src = wo; dst = g_wot; off = e - NX - NWQ - 2*NWK; }
        float4 v = *(const float4*)(src + off);
        uint4 u;
        u.x = f2tf32(v.x); u.y = f2tf32(v.y);
        u.z = f2tf32(v.z); u.w = f2tf32(v.w);
        *(uint4*)(dst + off) = u;
    }
}

// ===========================================================================
// tf32 tensor-core GEMM core: 256x128 CTA tile, 8 warps (4M x 2N),
// warp tile 64x64 -> 33% less smem-crossbar fragment traffic per output.
// ldmatrix fragment loads, 3-stage cp.async ring, one barrier per k-iter.
// OUT: 0 = fp32 direct, 1 = tf32 bits, 2 = tf32 bits transposed (C[col][row])
// ===========================================================================
#define GBK   32
#define GLDA  36
#define ABUF  (256 * GLDA)              // floats per A stage
#define BBUF  (128 * GLDA)              // floats per B stage
#define GSTG  3
#define GSMEM ((ABUF + BBUF) * GSTG * 4)   // 165888 bytes

template <int OUT>
__device__ __forceinline__ void gemm_core(
    const float* __restrict__ A, const float* __restrict__ W,
    const float* __restrict__ bias, float* __restrict__ C,
    int Nc, int row0)
{
    extern __shared__ float sm[];
    float* As = sm;                     // [GSTG][ABUF]
    float* Bs = sm + GSTG * ABUF;       // [GSTG][BBUF]

    const int tid  = threadIdx.x;
    const int K    = EE;

    // A staging: one thread per row, 8 consecutive cp16 (128 B)
    const float* Ag = A + (size_t)(row0 + tid) * K;
    const uint32_t Asd = cvta_s(As + tid * GLDA);
    // B staging: 2 threads per row, 4 consecutive cp16 (64 B) each
    const int rB = tid & 127;
    const int kb = (tid >> 7) * 16;
    const float* Wg = W + (size_t)rB * K + kb;
    const uint32_t Bsd = cvta_s(Bs + rB * GLDA + kb);

    const int lane = tid & 31;
    const int wid  = tid >> 5;
    const int wm   = (wid >> 1) * 64;   // 4 M-groups
    const int wn   = (wid & 1) * 64;    // 2 N-groups
    const int g    = lane >> 2;
    const int tig  = lane & 3;

    const uint32_t aoff =
        (uint32_t)(((wm + (lane & 15)) * GLDA + ((lane & 16) ? 4 : 0)) * 4);
    const uint32_t boff =
        (uint32_t)(((wn + (lane & 7) + ((lane & 16) ? 8 : 0)) * GLDA
                    + ((lane & 8) ? 4 : 0)) * 4);
    const uint32_t Abase0 = cvta_s(As);
    const uint32_t Bbase0 = cvta_s(Bs);

    float acc[4][8][4];
#pragma unroll
    for (int mt = 0; mt < 4; mt++)
#pragma unroll
        for (int nt = 0; nt < 8; nt++)
#pragma unroll
            for (int i = 0; i < 4; i++) acc[mt][nt][i] = 0.f;

    // prologue: stage k-chunks 0 and 1
#pragma unroll
    for (int s = 0; s < 2; s++) {
#pragma unroll
        for (int i = 0; i < 8; i++)
            cp16(Asd + s * ABUF * 4 + i * 16, Ag + s * GBK + i * 4);
#pragma unroll
        for (int i = 0; i < 4; i++)
            cp16(Bsd + s * BBUF * 4 + i * 16, Wg + s * GBK + i * 4);
        cp_commit();
    }

    const int NI = K / GBK;
    int bcur = 0, bpre = 2;
    for (int it = 0; it < NI; it++) {
        if (it + 1 < NI) cp_wait1(); else cp_wait0();
        __syncthreads();

        if (it + 2 < NI) {
            const float* a = Ag + (it + 2) * GBK;
            const float* w = Wg + (it + 2) * GBK;
            const uint32_t ad = Asd + bpre * ABUF * 4;
            const uint32_t bd = Bsd + bpre * BBUF * 4;
#pragma unroll
            for (int i = 0; i < 8; i++) cp16(ad + i * 16, a + i * 4);
#pragma unroll
            for (int i = 0; i < 4; i++) cp16(bd + i * 16, w + i * 4);
            cp_commit();
        }

        const uint32_t Ab = Abase0 + bcur * ABUF * 4 + aoff;
        const uint32_t Bb = Bbase0 + bcur * BBUF * 4 + boff;
#pragma unroll
        for (int ks = 0; ks < 4; ks++) {
            uint32_t a[4][4], b[4][4];
#pragma unroll
            for (int mt = 0; mt < 4; mt++)
                ldsm_x4(a[mt], Ab + (mt * 16 * GLDA + ks * 8) * 4);
#pragma unroll
            for (int np = 0; np < 4; np++)
                ldsm_x4(b[np], Bb + (np * 16 * GLDA + ks * 8) * 4);
#pragma unroll
            for (int mt = 0; mt < 4; mt++)
#pragma unroll
                for (int nt = 0; nt < 8; nt++)
                    mma_tf32(acc[mt][nt], a[mt], &b[nt >> 1][(nt & 1) * 2]);
        }

        bcur = (bcur + 1 == GSTG) ? 0 : bcur + 1;
        bpre = (bpre + 1 == GSTG) ? 0 : bpre + 1;
    }

#pragma unroll
    for (int mt = 0; mt < 4; mt++) {
        const int rowa = row0 + wm + mt * 16 + g;
#pragma unroll
        for (int nt = 0; nt < 8; nt++) {
            const int cola = wn + nt * 8 + 2 * tig;
            const float2 bv = *(const float2*)(bias + cola);
            float s0 = acc[mt][nt][0] + bv.x;
            float s1 = acc[mt][nt][1] + bv.y;
            float s2 = acc[mt][nt][2] + bv.x;
            float s3 = acc[mt][nt][3] + bv.y;
            if (OUT == 2) {        // transposed tf32 store: C[col * MM + row]
                C[(size_t)cola * MM + rowa]           = __uint_as_float(f2tf32(s0));
                C[(size_t)(cola + 1) * MM + rowa]     = __uint_as_float(f2tf32(s1));
                C[(size_t)cola * MM + rowa + 8]       = __uint_as_float(f2tf32(s2));
                C[(size_t)(cola + 1) * MM + rowa + 8] = __uint_as_float(f2tf32(s3));
            } else {
                float2 v0, v1;
                if (OUT == 1) {
                    v0.x = __uint_as_float(f2tf32(s0));
                    v0.y = __uint_as_float(f2tf32(s1));
                    v1.x = __uint_as_float(f2tf32(s2));
                    v1.y = __uint_as_float(f2tf32(s3));
                } else {
                    v0.x = s0; v0.y = s1; v1.x = s2; v1.y = s3;
                }
                *(float2*)(C + (size_t)rowa * Nc + cola)       = v0;
                *(float2*)(C + (size_t)(rowa + 8) * Nc + cola) = v1;
            }
        }
    }
}

// fused Q/K/V projection: tiles 0-7 -> Q, 8-9 -> K, 10-11 -> V(transposed)
__global__ void __launch_bounds__(256, 1)
gemm_qkv(float* Qo, float* Ko, float* Vto,
         const float* __restrict__ bq, const float* __restrict__ bk,
         const float* __restrict__ bv)
{
    const int bx   = blockIdx.x;
    const int row0 = blockIdx.y * 256;
    if (bx < 8) {
        const int c0 = bx * 128;
        gemm_core<1>(g_xt, g_wqt + (size_t)c0 * EE, bq + c0, Qo + c0, EE, row0);
    } else if (bx < 10) {
        const int c0 = (bx - 8) * 128;
        gemm_core<1>(g_xt, g_wkt + (size_t)c0 * EE, bk + c0, Ko + c0, KVE, row0);
    } else {
        const int c0 = (bx - 10) * 128;
        gemm_core<2>(g_xt, g_wvt + (size_t)c0 * EE, bv + c0,
                     Vto + (size_t)c0 * MM, KVE, row0);
    }
}

__global__ void __launch_bounds__(256, 1)
gemm_single(const float* __restrict__ A, const float* __restrict__ bias,
            float* __restrict__ C)
{
    const int c0 = blockIdx.x * 128;
    gemm_core<0>(A, g_wot + (size_t)c0 * EE, bias + c0, C + c0, EE,
                 blockIdx.y * 256);
}

// ===========================================================================
// Tensor-core flash attention (causal, GQA), tf32 mma.sync + ldmatrix.
// K smem [kv][d]; V smem [d][kv] (from transposed g_Vt); P smem [q][kv-chunk].
// 2-stage cp.async ring, one barrier per KV tile. (round-8, passing)
// ===========================================================================
#define PLD 68
#define KLD 68
#define VLD 68
#define FKB (64 * KLD)
#define FVB (64 * VLD)
#define FSMEM ((128 * PLD + 2 * FKB + 2 * FVB) * 4)   // 104448 bytes

__global__ void __launch_bounds__(256, 2)
flash_tc(const float* __restrict__ Q, const float* __restrict__ K,
         const float* __restrict__ Vt, float* __restrict__ O)
{
    extern __shared__ float fsm[];
    float* Ps = fsm;                 // [128][PLD]
    float* Kb = fsm + 128 * PLD;     // [2][64][KLD]  rows = kv pos
    float* Vb = Kb + 2 * FKB;        // [2][64][VLD]  rows = d

    const int tid  = threadIdx.x;
    const int lane = tid & 31;
    const int wid  = tid >> 5;
    const int g    = lane >> 2;
    const int tig  = lane & 3;
    const int m0   = (gridDim.x - 1 - blockIdx.x) * 128;   // heavy-first
    const int h    = blockIdx.y;
    const int b    = blockIdx.z;
    const int kvh  = h >> 2;

    const int sr  = tid >> 2;
    const int sc4 = (tid & 3) * 16;
    const float* kgb = K + ((size_t)(b * SS + sr)) * KVE + kvh * DD + sc4;
    const float* vgb = Vt + ((size_t)(kvh * DD + sr)) * MM + b * SS + sc4;
    const uint32_t kd0 = cvta_s(Kb + sr * KLD + sc4);
    const uint32_t vd0 = cvta_s(Vb + sr * VLD + sc4);

    const uint32_t koff =
        (uint32_t)((((lane & 7) + ((lane & 16) ? 8 : 0)) * KLD
                    + ((lane & 8) ? 4 : 0)) * 4);
    const uint32_t voff =
        (uint32_t)((((lane & 7) + ((lane & 16) ? 8 : 0)) * VLD
                    + ((lane & 8) ? 4 : 0)) * 4);
    const uint32_t poff =
        (uint32_t)(((wid * 16 + (lane & 15)) * PLD + ((lane & 16) ? 4 : 0)) * 4);
    const uint32_t Pbase = cvta_s(Ps);
    const uint32_t Kbase0 = cvta_s(Kb);
    const uint32_t Vbase0 = cvta_s(Vb);

    // stage Q (x 0.125: exact power of two on tf32 bits)
    {
        const int r  = tid >> 1;
        const int c0 = (tid & 1) * 32;
        const float* qg = Q + ((size_t)(b * SS + m0 + r)) * EE + h * DD + c0;
        float* dst = Ps + r * PLD + c0;
#pragma unroll
        for (int i = 0; i < 8; i++) {
            float4 v = *(const float4*)(qg + i * 4);
            dst[i * 4 + 0] = v.x * 0.125f;
            dst[i * 4 + 1] = v.y * 0.125f;
            dst[i * 4 + 2] = v.z * 0.125f;
            dst[i * 4 + 3] = v.w * 0.125f;
        }
    }

    const int ntile = m0 / 64 + 2;

#pragma unroll
    for (int i = 0; i < 4; i++) {
        cp16(kd0 + i * 16, kgb + i * 4);
        cp16(vd0 + i * 16, vgb + i * 4);
    }
    cp_commit();
    __syncthreads();                 // Q visible

    uint32_t qa[8][4];
    {
        const uint32_t* base = (const uint32_t*)(Ps + (wid * 16 + g) * PLD);
#pragma unroll
        for (int ks = 0; ks < 8; ks++) {
            qa[ks][0] = base[ks * 8 + tig];
            qa[ks][1] = base[8 * PLD + ks * 8 + tig];
            qa[ks][2] = base[ks * 8 + tig + 4];
            qa[ks][3] = base[8 * PLD + ks * 8 + tig + 4];
        }
    }

    float oacc[8][4];
#pragma unroll
    for (int nt = 0; nt < 8; nt++)
#pragma unroll
        for (int i = 0; i < 4; i++) oacc[nt][i] = 0.f;
    float mrow[2] = { -1e30f, -1e30f };
    float lrow[2] = { 0.f, 0.f };

    const int r0 = m0 + wid * 16 + g;

    for (int t = 0; t < ntile; t++) {
        const int cb = t & 1;

        cp_wait0();
        __syncthreads();

        if (t + 1 < ntile) {
            const float* kg = kgb + (size_t)((t + 1) * 64) * KVE;
            const float* vg = vgb + (t + 1) * 64;
            const uint32_t kd = kd0 + (1 - cb) * FKB * 4;
            const uint32_t vd = vd0 + (1 - cb) * FVB * 4;
#pragma unroll
            for (int i = 0; i < 4; i++) {
                cp16(kd + i * 16, kg + i * 4);
                cp16(vd + i * 16, vg + i * 4);
            }
            cp_commit();
        }

        const int j0 = t * 64;
        const bool active = (j0 <= m0 + wid * 16 + 15);    // warp-uniform
        if (active) {
            const uint32_t Kc = Kbase0 + cb * FKB * 4 + koff;
            const uint32_t Vc = Vbase0 + cb * FVB * 4 + voff;

            // S = Q @ K^T
            float sc[8][4];
#pragma unroll
            for (int nt = 0; nt < 8; nt++)
#pragma unroll
                for (int i = 0; i < 4; i++) sc[nt][i] = 0.f;
#pragma unroll
            for (int ks = 0; ks < 8; ks++) {
                uint32_t kb2[4][4];
#pragma unroll
                for (int np = 0; np < 4; np++)
                    ldsm_x4(kb2[np], Kc + (np * 16 * KLD + ks * 8) * 4);
#pragma unroll
                for (int nt = 0; nt < 8; nt++)
                    mma_tf32(sc[nt], qa[ks], &kb2[nt >> 1][(nt & 1) * 2]);
            }

            // causal mask (diagonal tiles only)
            if (j0 + 63 > r0) {
#pragma unroll
                for (int nt = 0; nt < 8; nt++) {
                    const int c = j0 + nt * 8 + 2 * tig;
                    if (c     > r0)     sc[nt][0] = -1e30f;
                    if (c + 1 > r0)     sc[nt][1] = -1e30f;
                    if (c     > r0 + 8) sc[nt][2] = -1e30f;
                    if (c + 1 > r0 + 8) sc[nt][3] = -1e30f;
                }
            }

            // row max (quad reduce)
            float tm0 = -1e30f, tm1 = -1e30f;
#pragma unroll
            for (int nt = 0; nt < 8; nt++) {
                tm0 = fmaxf(tm0, fmaxf(sc[nt][0], sc[nt][1]));
                tm1 = fmaxf(tm1, fmaxf(sc[nt][2], sc[nt][3]));
            }
            tm0 = fmaxf(tm0, __shfl_xor_sync(0xffffffffu, tm0, 1));
            tm0 = fmaxf(tm0, __shfl_xor_sync(0xffffffffu, tm0, 2));
            tm1 = fmaxf(tm1, __shfl_xor_sync(0xffffffffu, tm1, 1));
            tm1 = fmaxf(tm1, __shfl_xor_sync(0xffffffffu, tm1, 2));

            const float mn0 = fmaxf(mrow[0], tm0);
            const float mn1 = fmaxf(mrow[1], tm1);
            const float cr0 = __expf(mrow[0] - mn0);
            const float cr1 = __expf(mrow[1] - mn1);
            mrow[0] = mn0; mrow[1] = mn1;

            float ls0 = 0.f, ls1 = 0.f;
#pragma unroll
            for (int nt = 0; nt < 8; nt++) {
                sc[nt][0] = __expf(sc[nt][0] - mn0); ls0 += sc[nt][0];
                sc[nt][1] = __expf(sc[nt][1] - mn0); ls0 += sc[nt][1];
                sc[nt][2] = __expf(sc[nt][2] - mn1); ls1 += sc[nt][2];
                sc[nt][3] = __expf(sc[nt][3] - mn1); ls1 += sc[nt][3];
            }
            lrow[0] = lrow[0] * cr0 + ls0;
            lrow[1] = lrow[1] * cr1 + ls1;
#pragma unroll
            for (int nt = 0; nt < 8; nt++) {
                oacc[nt][0] *= cr0; oacc[nt][1] *= cr0;
                oacc[nt][2] *= cr1; oacc[nt][3] *= cr1;
            }

            // P -> smem (tf32 bits), warp-private rows
            uint32_t* pr = (uint32_t*)(Ps + (wid * 16 + g) * PLD);
#pragma unroll
            for (int nt = 0; nt < 8; nt++) {
                uint2 w0, w1;
                w0.x = f2tf32(sc[nt][0]); w0.y = f2tf32(sc[nt][1]);
                w1.x = f2tf32(sc[nt][2]); w1.y = f2tf32(sc[nt][3]);
                *(uint2*)(pr + nt * 8 + 2 * tig)           = w0;
                *(uint2*)(pr + 8 * PLD + nt * 8 + 2 * tig) = w1;
            }
            __syncwarp();

            // O += P @ V  (P and V fragments via ldmatrix)
#pragma unroll
            for (int ks = 0; ks < 8; ks++) {
                uint32_t pa[4], vb2[4][4];
                ldsm_x4(pa, Pbase + poff + ks * 8 * 4);
#pragma unroll
                for (int np = 0; np < 4; np++)
                    ldsm_x4(vb2[np], Vc + (np * 16 * VLD + ks * 8) * 4);
#pragma unroll
                for (int nt = 0; nt < 8; nt++)
                    mma_tf32(oacc[nt], pa, &vb2[nt >> 1][(nt & 1) * 2]);
            }
        }
    }

    // finalize: store context as tf32 bits (consumed by gemm_single MMA)
    lrow[0] += __shfl_xor_sync(0xffffffffu, lrow[0], 1);
    lrow[0] += __shfl_xor_sync(0xffffffffu, lrow[0], 2);
    lrow[1] += __shfl_xor_sync(0xffffffffu, lrow[1], 1);
    lrow[1] += __shfl_xor_sync(0xffffffffu, lrow[1], 2);
    const float inv0 = 1.f / lrow[0];
    const float inv1 = 1.f / lrow[1];

    float* og = O + ((size_t)(b * SS + r0)) * EE + h * DD;
#pragma unroll
    for (int nt = 0; nt < 8; nt++) {
        float2 v0, v1;
        v0.x = __uint_as_float(f2tf32(oacc[nt][0] * inv0));
        v0.y = __uint_as_float(f2tf32(oacc[nt][1] * inv0));
        v1.x = __uint_as_float(f2tf32(oacc[nt][2] * inv1));
        v1.y = __uint_as_float(f2tf32(oacc[nt][3] * inv1));
        *(float2*)(og + nt * 8 + 2 * tig)                  = v0;
        *(float2*)(og + (size_t)8 * EE + nt * 8 + 2 * tig) = v1;
    }
}

// ---------------------------------------------------------------------------
// Launch
// ---------------------------------------------------------------------------
extern "C" void kernel_launch(void* const* d_in, const int* in_sizes, int n_in,
                              void* d_out, int out_size)
{
    const float* x    = (const float*)d_in[0];
    // d_in[1] is the causal mask (triu, k=1) — applied analytically (j<=i).
    const float* wq_w = (const float*)d_in[2];
    const float* wq_b = (const float*)d_in[3];
    const float* wk_w = (const float*)d_in[4];
    const float* wk_b = (const float*)d_in[5];
    const float* wv_w = (const float*)d_in[6];
    const float* wv_b = (const float*)d_in[7];
    const float* wo_w = (const float*)d_in[8];
    const float* wo_b = (const float*)d_in[9];
    float* out = (float*)d_out;

    float *Qp, *Kp, *Vtp, *Cp;
    cudaGetSymbolAddress((void**)&Qp, g_Q);
    cudaGetSymbolAddress((void**)&Kp, g_K);
    cudaGetSymbolAddress((void**)&Vtp, g_Vt);
    cudaGetSymbolAddress((void**)&Cp, g_C);

    cudaFuncSetAttribute(gemm_qkv,
                         cudaFuncAttributeMaxDynamicSharedMemorySize, GSMEM);
    cudaFuncSetAttribute(gemm_single,
                         cudaFuncAttributeMaxDynamicSharedMemorySize, GSMEM);
    cudaFuncSetAttribute(flash_tc,
                         cudaFuncAttributeMaxDynamicSharedMemorySize, FSMEM);

    // convert x + weights to tf32 storage
    prep_tf32<<<1024, 256>>>(x, wq_w, wk_w, wv_w, wo_w);

    // fused Q/K/V projections (V written transposed)
    gemm_qkv<<<dim3(12, MM / 256), 256, GSMEM>>>(Qp, Kp, Vtp, wq_b, wk_b, wv_b);

    // causal GQA flash attention
    flash_tc<<<dim3(SS / 128, HH, BB), 256, FSMEM>>>(Qp, Kp, Vtp, Cp);

    // output projection
    gemm_single<<<dim3(EE / 128, MM / 256), 256, GSMEM>>>(Cp, wo_b, out);
}

// round 10
// speedup vs baseline: 1.0434x; 1.0434x over previous
#include <cuda_runtime.h>
#include <cuda_bf16.h>
#include <cstdint>

// Problem constants
#define BB   2
#define SS   2048
#define EE   1024
#define HH   16
#define HKV  4
#define DD   64
#define KVE  (HKV * DD)   // 256
#define MM   (BB * SS)    // 4096

// Scratch (allocation-free rule: __device__ globals)
__device__ float g_Q[(size_t)MM * EE];     // tf32-bit Q
__device__ float g_K[(size_t)MM * KVE];    // tf32-bit K
__device__ float g_Vt[(size_t)KVE * MM];   // tf32-bit V, TRANSPOSED [d][pos]
__device__ float g_C[(size_t)MM * EE];     // tf32-bit context
__device__ float g_xt[(size_t)MM * EE];    // tf32-bit x
__device__ float g_wqt[(size_t)EE * EE];   // tf32-bit weights
__device__ float g_wkt[(size_t)KVE * EE];
__device__ float g_wvt[(size_t)KVE * EE];
__device__ float g_wot[(size_t)EE * EE];

__device__ __forceinline__ uint32_t f2tf32(float x) {
    uint32_t u;
    asm("cvt.rna.tf32.f32 %0, %1;" : "=r"(u) : "f"(x));
    return u;
}
__device__ __forceinline__ void mma_tf32(float* c, const uint32_t* a,
                                         const uint32_t* b) {
    asm volatile(
        "mma.sync.aligned.m16n8k8.row.col.f32.tf32.tf32.f32 "
        "{%0,%1,%2,%3}, {%4,%5,%6,%7}, {%8,%9}, {%0,%1,%2,%3};"
        : "+f"(c[0]), "+f"(c[1]), "+f"(c[2]), "+f"(c[3])
        : "r"(a[0]), "r"(a[1]), "r"(a[2]), "r"(a[3]),
          "r"(b[0]), "r"(b[1]));
}
__device__ __forceinline__ void ldsm_x4(uint32_t* r, uint32_t addr) {
    asm volatile("ldmatrix.sync.aligned.m8n8.x4.shared.b16 {%0,%1,%2,%3}, [%4];"
                 : "=r"(r[0]), "=r"(r[1]), "=r"(r[2]), "=r"(r[3])
                 : "r"(addr));
}
__device__ __forceinline__ void cp16(uint32_t d, const void* s) {
    asm volatile("cp.async.cg.shared.global [%0], [%1], 16;"
                 :: "r"(d), "l"(s) : "memory");
}
__device__ __forceinline__ void cp_commit() {
    asm volatile("cp.async.commit_group;" ::: "memory");
}
__device__ __forceinline__ void cp_wait0() {
    asm volatile("cp.async.wait_group 0;" ::: "memory");
}
__device__ __forceinline__ void cp_wait1() {
    asm volatile("cp.async.wait_group 1;" ::: "memory");
}
__device__ __forceinline__ uint32_t cvta_s(const void* p) {
    return (uint32_t)__cvta_generic_to_shared(p);
}

// ===========================================================================
// Prep: convert x + all weights to tf32 bit patterns (stored as float)
// ===========================================================================
#define NX  (MM * EE)
#define NWQ (EE * EE)
#define NWK (KVE * EE)
#define NTOT (NX + NWQ + 2 * NWK + NWQ)

__global__ void __launch_bounds__(256)
prep_tf32(const float* __restrict__ x,
          const float* __restrict__ wq, const float* __restrict__ wk,
          const float* __restrict__ wv, const float* __restrict__ wo)
{
    const int nvec = NTOT / 4;
    for (int i = blockIdx.x * blockDim.x + threadIdx.x; i < nvec;
         i += gridDim.x * blockDim.x) {
        const int e = i * 4;
        const float* src;
        float* dst;
        int off;
        if (e < NX)                    { src = x;  dst = g_xt;  off = e; }
        else if (e < NX + NWQ)         { src = wq; dst = g_wqt; off = e - NX; }
        else if (e < NX + NWQ + NWK)   { src = wk; dst = g_wkt; off = e - NX - NWQ; }
        else if (e < NX + NWQ + 2*NWK) { src = wv; dst = g_wvt; off = e - NX - NWQ - NWK; }
        else                           { src = wo; dst = g_wot; off = e - NX - NWQ - 2*NWK; }
        float4 v = *(const float4*)(src + off);
        uint4 u;
        u.x = f2tf32(v.x); u.y = f2tf32(v.y);
        u.z = f2tf32(v.z); u.w = f2tf32(v.w);
        *(uint4*)(dst + off) = u;
    }
}

// ===========================================================================
// tf32 tensor-core GEMM core: 128x128 CTA tile, 128 threads (4 warps, 2x2),
// warp tile 64x64 -> 33% less fragment crossbar traffic than 8x(64x32),
// while smem stays 110.6KB so 2 CTAs/SM co-reside (barrier coverage).
// ldmatrix fragment loads, 3-stage cp.async ring, one barrier per k-iter.
// OUT: 0 = fp32 direct, 1 = tf32 bits, 2 = tf32 bits transposed (C[col][row])
// ===========================================================================
#define GBK   32
#define GLDA  36
#define GBUF  (128 * GLDA)              // floats per (A or B) stage
#define GSTG  3
#define GSMEM (2 * GSTG * GBUF * 4)     // 110592 bytes

template <int OUT>
__device__ __forceinline__ void gemm_core(
    const float* __restrict__ A, const float* __restrict__ W,
    const float* __restrict__ bias, float* __restrict__ C,
    int Nc, int row0)
{
    extern __shared__ float sm[];
    float* As = sm;                     // [GSTG][GBUF]
    float* Bs = sm + GSTG * GBUF;       // [GSTG][GBUF]

    const int tid  = threadIdx.x;       // 0..127
    const int K    = EE;

    // staging: one thread per row, 8 cp16 (128 B) each for A and B
    const float* Ag = A + (size_t)(row0 + tid) * K;
    const float* Wg = W + (size_t)tid * K;
    const uint32_t Asd = cvta_s(As + tid * GLDA);
    const uint32_t Bsd = cvta_s(Bs + tid * GLDA);

    const int lane = tid & 31;
    const int wid  = tid >> 5;          // 0..3
    const int wm   = (wid >> 1) * 64;   // 2 M-groups
    const int wn   = (wid & 1) * 64;    // 2 N-groups
    const int g    = lane >> 2;
    const int tig  = lane & 3;

    const uint32_t aoff =
        (uint32_t)(((wm + (lane & 15)) * GLDA + ((lane & 16) ? 4 : 0)) * 4);
    const uint32_t boff =
        (uint32_t)(((wn + (lane & 7) + ((lane & 16) ? 8 : 0)) * GLDA
                    + ((lane & 8) ? 4 : 0)) * 4);
    const uint32_t Abase0 = cvta_s(As);
    const uint32_t Bbase0 = cvta_s(Bs);

    float acc[4][8][4];
#pragma unroll
    for (int mt = 0; mt < 4; mt++)
#pragma unroll
        for (int nt = 0; nt < 8; nt++)
#pragma unroll
            for (int i = 0; i < 4; i++) acc[mt][nt][i] = 0.f;

    // prologue: stage k-chunks 0 and 1
#pragma unroll
    for (int s = 0; s < 2; s++) {
#pragma unroll
        for (int i = 0; i < 8; i++) {
            cp16(Asd + s * GBUF * 4 + i * 16, Ag + s * GBK + i * 4);
            cp16(Bsd + s * GBUF * 4 + i * 16, Wg + s * GBK + i * 4);
        }
        cp_commit();
    }

    const int NI = K / GBK;
    int bcur = 0, bpre = 2;
    for (int it = 0; it < NI; it++) {
        if (it + 1 < NI) cp_wait1(); else cp_wait0();
        __syncthreads();

        if (it + 2 < NI) {
            const float* a = Ag + (it + 2) * GBK;
            const float* w = Wg + (it + 2) * GBK;
            const uint32_t ad = Asd + bpre * GBUF * 4;
            const uint32_t bd = Bsd + bpre * GBUF * 4;
#pragma unroll
            for (int i = 0; i < 8; i++) {
                cp16(ad + i * 16, a + i * 4);
                cp16(bd + i * 16, w + i * 4);
            }
            cp_commit();
        }

        const uint32_t Ab = Abase0 + bcur * GBUF * 4 + aoff;
        const uint32_t Bb = Bbase0 + bcur * GBUF * 4 + boff;
#pragma unroll
        for (int ks = 0; ks < 4; ks++) {
            uint32_t a[4][4], b[4][4];
#pragma unroll
            for (int mt = 0; mt < 4; mt++)
                ldsm_x4(a[mt], Ab + (mt * 16 * GLDA + ks * 8) * 4);
#pragma unroll
            for (int np = 0; np < 4; np++)
                ldsm_x4(b[np], Bb + (np * 16 * GLDA + ks * 8) * 4);
#pragma unroll
            for (int mt = 0; mt < 4; mt++)
#pragma unroll
                for (int nt = 0; nt < 8; nt++)
                    mma_tf32(acc[mt][nt], a[mt], &b[nt >> 1][(nt & 1) * 2]);
        }

        bcur = (bcur + 1 == GSTG) ? 0 : bcur + 1;
        bpre = (bpre + 1 == GSTG) ? 0 : bpre + 1;
    }

#pragma unroll
    for (int mt = 0; mt < 4; mt++) {
        const int rowa = row0 + wm + mt * 16 + g;
#pragma unroll
        for (int nt = 0; nt < 8; nt++) {
            const int cola = wn + nt * 8 + 2 * tig;
            const float2 bv = *(const float2*)(bias + cola);
            float s0 = acc[mt][nt][0] + bv.x;
            float s1 = acc[mt][nt][1] + bv.y;
            float s2 = acc[mt][nt][2] + bv.x;
            float s3 = acc[mt][nt][3] + bv.y;
            if (OUT == 2) {        // transposed tf32 store: C[col * MM + row]
                C[(size_t)cola * MM + rowa]           = __uint_as_float(f2tf32(s0));
                C[(size_t)(cola + 1) * MM + rowa]     = __uint_as_float(f2tf32(s1));
                C[(size_t)cola * MM + rowa + 8]       = __uint_as_float(f2tf32(s2));
                C[(size_t)(cola + 1) * MM + rowa + 8] = __uint_as_float(f2tf32(s3));
            } else {
                float2 v0, v1;
                if (OUT == 1) {
                    v0.x = __uint_as_float(f2tf32(s0));
                    v0.y = __uint_as_float(f2tf32(s1));
                    v1.x = __uint_as_float(f2tf32(s2));
                    v1.y = __uint_as_float(f2tf32(s3));
                } else {
                    v0.x = s0; v0.y = s1; v1.x = s2; v1.y = s3;
                }
                *(float2*)(C + (size_t)rowa * Nc + cola)       = v0;
                *(float2*)(C + (size_t)(rowa + 8) * Nc + cola) = v1;
            }
        }
    }
}

// fused Q/K/V projection: tiles 0-7 -> Q, 8-9 -> K, 10-11 -> V(transposed)
__global__ void __launch_bounds__(128, 2)
gemm_qkv(float* Qo, float* Ko, float* Vto,
         const float* __restrict__ bq, const float* __restrict__ bk,
         const float* __restrict__ bv)
{
    const int bx   = blockIdx.x;
    const int row0 = blockIdx.y * 128;
    if (bx < 8) {
        const int c0 = bx * 128;
        gemm_core<1>(g_xt, g_wqt + (size_t)c0 * EE, bq + c0, Qo + c0, EE, row0);
    } else if (bx < 10) {
        const int c0 = (bx - 8) * 128;
        gemm_core<1>(g_xt, g_wkt + (size_t)c0 * EE, bk + c0, Ko + c0, KVE, row0);
    } else {
        const int c0 = (bx - 10) * 128;
        gemm_core<2>(g_xt, g_wvt + (size_t)c0 * EE, bv + c0,
                     Vto + (size_t)c0 * MM, KVE, row0);
    }
}

__global__ void __launch_bounds__(128, 2)
gemm_single(const float* __restrict__ A, const float* __restrict__ bias,
            float* __restrict__ C)
{
    const int c0 = blockIdx.x * 128;
    gemm_core<0>(A, g_wot + (size_t)c0 * EE, bias + c0, C + c0, EE,
                 blockIdx.y * 128);
}

// ===========================================================================
// Tensor-core flash attention (causal, GQA), tf32 mma.sync + ldmatrix.
// K smem [kv][d]; V smem [d][kv] (from transposed g_Vt); P smem [q][kv-chunk].
// 2-stage cp.async ring, one barrier per KV tile. (round-8, passing, 422us)
// ===========================================================================
#define PLD 68
#define KLD 68
#define VLD 68
#define FKB (64 * KLD)
#define FVB (64 * VLD)
#define FSMEM ((128 * PLD + 2 * FKB + 2 * FVB) * 4)   // 104448 bytes

__global__ void __launch_bounds__(256, 2)
flash_tc(const float* __restrict__ Q, const float* __restrict__ K,
         const float* __restrict__ Vt, float* __restrict__ O)
{
    extern __shared__ float fsm[];
    float* Ps = fsm;                 // [128][PLD]
    float* Kb = fsm + 128 * PLD;     // [2][64][KLD]  rows = kv pos
    float* Vb = Kb + 2 * FKB;        // [2][64][VLD]  rows = d

    const int tid  = threadIdx.x;
    const int lane = tid & 31;
    const int wid  = tid >> 5;
    const int g    = lane >> 2;
    const int tig  = lane & 3;
    const int m0   = (gridDim.x - 1 - blockIdx.x) * 128;   // heavy-first
    const int h    = blockIdx.y;
    const int b    = blockIdx.z;
    const int kvh  = h >> 2;

    const int sr  = tid >> 2;
    const int sc4 = (tid & 3) * 16;
    const float* kgb = K + ((size_t)(b * SS + sr)) * KVE + kvh * DD + sc4;
    const float* vgb = Vt + ((size_t)(kvh * DD + sr)) * MM + b * SS + sc4;
    const uint32_t kd0 = cvta_s(Kb + sr * KLD + sc4);
    const uint32_t vd0 = cvta_s(Vb + sr * VLD + sc4);

    const uint32_t koff =
        (uint32_t)((((lane & 7) + ((lane & 16) ? 8 : 0)) * KLD
                    + ((lane & 8) ? 4 : 0)) * 4);
    const uint32_t voff =
        (uint32_t)((((lane & 7) + ((lane & 16) ? 8 : 0)) * VLD
                    + ((lane & 8) ? 4 : 0)) * 4);
    const uint32_t poff =
        (uint32_t)(((wid * 16 + (lane & 15)) * PLD + ((lane & 16) ? 4 : 0)) * 4);
    const uint32_t Pbase = cvta_s(Ps);
    const uint32_t Kbase0 = cvta_s(Kb);
    const uint32_t Vbase0 = cvta_s(Vb);

    // stage Q (x 0.125: exact power of two on tf32 bits)
    {
        const int r  = tid >> 1;
        const int c0 = (tid & 1) * 32;
        const float* qg = Q + ((size_t)(b * SS + m0 + r)) * EE + h * DD + c0;
        float* dst = Ps + r * PLD + c0;
#pragma unroll
        for (int i = 0; i < 8; i++) {
            float4 v = *(const float4*)(qg + i * 4);
            dst[i * 4 + 0] = v.x * 0.125f;
            dst[i * 4 + 1] = v.y * 0.125f;
            dst[i * 4 + 2] = v.z * 0.125f;
            dst[i * 4 + 3] = v.w * 0.125f;
        }
    }

    const int ntile = m0 / 64 + 2;

#pragma unroll
    for (int i = 0; i < 4; i++) {
        cp16(kd0 + i * 16, kgb + i * 4);
        cp16(vd0 + i * 16, vgb + i * 4);
    }
    cp_commit();
    __syncthreads();                 // Q visible

    uint32_t qa[8][4];
    {
        const uint32_t* base = (const uint32_t*)(Ps + (wid * 16 + g) * PLD);
#pragma unroll
        for (int ks = 0; ks < 8; ks++) {
            qa[ks][0] = base[ks * 8 + tig];
            qa[ks][1] = base[8 * PLD + ks * 8 + tig];
            qa[ks][2] = base[ks * 8 + tig + 4];
            qa[ks][3] = base[8 * PLD + ks * 8 + tig + 4];
        }
    }

    float oacc[8][4];
#pragma unroll
    for (int nt = 0; nt < 8; nt++)
#pragma unroll
        for (int i = 0; i < 4; i++) oacc[nt][i] = 0.f;
    float mrow[2] = { -1e30f, -1e30f };
    float lrow[2] = { 0.f, 0.f };

    const int r0 = m0 + wid * 16 + g;

    for (int t = 0; t < ntile; t++) {
        const int cb = t & 1;

        cp_wait0();
        __syncthreads();

        if (t + 1 < ntile) {
            const float* kg = kgb + (size_t)((t + 1) * 64) * KVE;
            const float* vg = vgb + (t + 1) * 64;
            const uint32_t kd = kd0 + (1 - cb) * FKB * 4;
            const uint32_t vd = vd0 + (1 - cb) * FVB * 4;
#pragma unroll
            for (int i = 0; i < 4; i++) {
                cp16(kd + i * 16, kg + i * 4);
                cp16(vd + i * 16, vg + i * 4);
            }
            cp_commit();
        }

        const int j0 = t * 64;
        const bool active = (j0 <= m0 + wid * 16 + 15);    // warp-uniform
        if (active) {
            const uint32_t Kc = Kbase0 + cb * FKB * 4 + koff;
            const uint32_t Vc = Vbase0 + cb * FVB * 4 + voff;

            // S = Q @ K^T
            float sc[8][4];
#pragma unroll
            for (int nt = 0; nt < 8; nt++)
#pragma unroll
                for (int i = 0; i < 4; i++) sc[nt][i] = 0.f;
#pragma unroll
            for (int ks = 0; ks < 8; ks++) {
                uint32_t kb2[4][4];
#pragma unroll
                for (int np = 0; np < 4; np++)
                    ldsm_x4(kb2[np], Kc + (np * 16 * KLD + ks * 8) * 4);
#pragma unroll
                for (int nt = 0; nt < 8; nt++)
                    mma_tf32(sc[nt], qa[ks], &kb2[nt >> 1][(nt & 1) * 2]);
            }

            // causal mask (diagonal tiles only)
            if (j0 + 63 > r0) {
#pragma unroll
                for (int nt = 0; nt < 8; nt++) {
                    const int c = j0 + nt * 8 + 2 * tig;
                    if (c     > r0)     sc[nt][0] = -1e30f;
                    if (c + 1 > r0)     sc[nt][1] = -1e30f;
                    if (c     > r0 + 8) sc[nt][2] = -1e30f;
                    if (c + 1 > r0 + 8) sc[nt][3] = -1e30f;
                }
            }

            // row max (quad reduce)
            float tm0 = -1e30f, tm1 = -1e30f;
#pragma unroll
            for (int nt = 0; nt < 8; nt++) {
                tm0 = fmaxf(tm0, fmaxf(sc[nt][0], sc[nt][1]));
                tm1 = fmaxf(tm1, fmaxf(sc[nt][2], sc[nt][3]));
            }
            tm0 = fmaxf(tm0, __shfl_xor_sync(0xffffffffu, tm0, 1));
            tm0 = fmaxf(tm0, __shfl_xor_sync(0xffffffffu, tm0, 2));
            tm1 = fmaxf(tm1, __shfl_xor_sync(0xffffffffu, tm1, 1));
            tm1 = fmaxf(tm1, __shfl_xor_sync(0xffffffffu, tm1, 2));

            const float mn0 = fmaxf(mrow[0], tm0);
            const float mn1 = fmaxf(mrow[1], tm1);
            const float cr0 = __expf(mrow[0] - mn0);
            const float cr1 = __expf(mrow[1] - mn1);
            mrow[0] = mn0; mrow[1] = mn1;

            float ls0 = 0.f, ls1 = 0.f;
#pragma unroll
            for (int nt = 0; nt < 8; nt++) {
                sc[nt][0] = __expf(sc[nt][0] - mn0); ls0 += sc[nt][0];
                sc[nt][1] = __expf(sc[nt][1] - mn0); ls0 += sc[nt][1];
                sc[nt][2] = __expf(sc[nt][2] - mn1); ls1 += sc[nt][2];
                sc[nt][3] = __expf(sc[nt][3] - mn1); ls1 += sc[nt][3];
            }
            lrow[0] = lrow[0] * cr0 + ls0;
            lrow[1] = lrow[1] * cr1 + ls1;
#pragma unroll
            for (int nt = 0; nt < 8; nt++) {
                oacc[nt][0] *= cr0; oacc[nt][1] *= cr0;
                oacc[nt][2] *= cr1; oacc[nt][3] *= cr1;
            }

            // P -> smem (tf32 bits), warp-private rows
            uint32_t* pr = (uint32_t*)(Ps + (wid * 16 + g) * PLD);
#pragma unroll
            for (int nt = 0; nt < 8; nt++) {
                uint2 w0, w1;
                w0.x = f2tf32(sc[nt][0]); w0.y = f2tf32(sc[nt][1]);
                w1.x = f2tf32(sc[nt][2]); w1.y = f2tf32(sc[nt][3]);
                *(uint2*)(pr + nt * 8 + 2 * tig)           = w0;
                *(uint2*)(pr + 8 * PLD + nt * 8 + 2 * tig) = w1;
            }
            __syncwarp();

            // O += P @ V  (P and V fragments via ldmatrix)
#pragma unroll
            for (int ks = 0; ks < 8; ks++) {
                uint32_t pa[4], vb2[4][4];
                ldsm_x4(pa, Pbase + poff + ks * 8 * 4);
#pragma unroll
                for (int np = 0; np < 4; np++)
                    ldsm_x4(vb2[np], Vc + (np * 16 * VLD + ks * 8) * 4);
#pragma unroll
                for (int nt = 0; nt < 8; nt++)
                    mma_tf32(oacc[nt], pa, &vb2[nt >> 1][(nt & 1) * 2]);
            }
        }
    }

    // finalize: store context as tf32 bits (consumed by gemm_single MMA)
    lrow[0] += __shfl_xor_sync(0xffffffffu, lrow[0], 1);
    lrow[0] += __shfl_xor_sync(0xffffffffu, lrow[0], 2);
    lrow[1] += __shfl_xor_sync(0xffffffffu, lrow[1], 1);
    lrow[1] += __shfl_xor_sync(0xffffffffu, lrow[1], 2);
    const float inv0 = 1.f / lrow[0];
    const float inv1 = 1.f / lrow[1];

    float* og = O + ((size_t)(b * SS + r0)) * EE + h * DD;
#pragma unroll
    for (int nt = 0; nt < 8; nt++) {
        float2 v0, v1;
        v0.x = __uint_as_float(f2tf32(oacc[nt][0] * inv0));
        v0.y = __uint_as_float(f2tf32(oacc[nt][1] * inv0));
        v1.x = __uint_as_float(f2tf32(oacc[nt][2] * inv1));
        v1.y = __uint_as_float(f2tf32(oacc[nt][3] * inv1));
        *(float2*)(og + nt * 8 + 2 * tig)                  = v0;
        *(float2*)(og + (size_t)8 * EE + nt * 8 + 2 * tig) = v1;
    }
}

// ---------------------------------------------------------------------------
// Launch
// ---------------------------------------------------------------------------
extern "C" void kernel_launch(void* const* d_in, const int* in_sizes, int n_in,
                              void* d_out, int out_size)
{
    const float* x    = (const float*)d_in[0];
    // d_in[1] is the causal mask (triu, k=1) — applied analytically (j<=i).
    const float* wq_w = (const float*)d_in[2];
    const float* wq_b = (const float*)d_in[3];
    const float* wk_w = (const float*)d_in[4];
    const float* wk_b = (const float*)d_in[5];
    const float* wv_w = (const float*)d_in[6];
    const float* wv_b = (const float*)d_in[7];
    const float* wo_w = (const float*)d_in[8];
    const float* wo_b = (const float*)d_in[9];
    float* out = (float*)d_out;

    float *Qp, *Kp, *Vtp, *Cp;
    cudaGetSymbolAddress((void**)&Qp, g_Q);
    cudaGetSymbolAddress((void**)&Kp, g_K);
    cudaGetSymbolAddress((void**)&Vtp, g_Vt);
    cudaGetSymbolAddress((void**)&Cp, g_C);

    cudaFuncSetAttribute(gemm_qkv,
                         cudaFuncAttributeMaxDynamicSharedMemorySize, GSMEM);
    cudaFuncSetAttribute(gemm_single,
                         cudaFuncAttributeMaxDynamicSharedMemorySize, GSMEM);
    cudaFuncSetAttribute(flash_tc,
                         cudaFuncAttributeMaxDynamicSharedMemorySize, FSMEM);

    // convert x + weights to tf32 storage
    prep_tf32<<<1024, 256>>>(x, wq_w, wk_w, wv_w, wo_w);

    // fused Q/K/V projections (V written transposed)
    gemm_qkv<<<dim3(12, MM / 128), 128, GSMEM>>>(Qp, Kp, Vtp, wq_b, wk_b, wv_b);

    // causal GQA flash attention
    flash_tc<<<dim3(SS / 128, HH, BB), 256, FSMEM>>>(Qp, Kp, Vtp, Cp);

    // output projection
    gemm_single<<<dim3(EE / 128, MM / 128), 128, GSMEM>>>(Cp, wo_b, out);
}

// round 11
// speedup vs baseline: 2.1609x; 2.0710x over previous
#include <cuda_runtime.h>
#include <cuda_fp16.h>
#include <cstdint>

// Problem constants
#define BB   2
#define SS   2048
#define EE   1024
#define HH   16
#define HKV  4
#define DD   64
#define KVE  (HKV * DD)   // 256
#define MM   (BB * SS)    // 4096

// Scratch (allocation-free rule: __device__ globals) — all fp16
__device__ __half g_Qh[(size_t)MM * EE];    // Q (pre-scaled by 1/8)
__device__ __half g_Kh[(size_t)MM * KVE];   // K
__device__ __half g_Vth[(size_t)KVE * MM];  // V transposed [d][pos]
__device__ __half g_Ch[(size_t)MM * EE];    // context
__device__ __half g_xh[(size_t)MM * EE];    // x
__device__ __half g_wqh[(size_t)EE * EE];
__device__ __half g_wkh[(size_t)KVE * EE];
__device__ __half g_wvh[(size_t)KVE * EE];
__device__ __half g_woh[(size_t)EE * EE];

__device__ __forceinline__ void mma_f16(float* c, const uint32_t* a,
                                        uint32_t b0, uint32_t b1) {
    asm volatile(
        "mma.sync.aligned.m16n8k16.row.col.f32.f16.f16.f32 "
        "{%0,%1,%2,%3}, {%4,%5,%6,%7}, {%8,%9}, {%0,%1,%2,%3};"
        : "+f"(c[0]), "+f"(c[1]), "+f"(c[2]), "+f"(c[3])
        : "r"(a[0]), "r"(a[1]), "r"(a[2]), "r"(a[3]), "r"(b0), "r"(b1));
}
__device__ __forceinline__ void ldsm_x4(uint32_t* r, uint32_t addr) {
    asm volatile("ldmatrix.sync.aligned.m8n8.x4.shared.b16 {%0,%1,%2,%3}, [%4];"
                 : "=r"(r[0]), "=r"(r[1]), "=r"(r[2]), "=r"(r[3])
                 : "r"(addr));
}
__device__ __forceinline__ void cp16(uint32_t d, const void* s) {
    asm volatile("cp.async.cg.shared.global [%0], [%1], 16;"
                 :: "r"(d), "l"(s) : "memory");
}
__device__ __forceinline__ void cp_commit() {
    asm volatile("cp.async.commit_group;" ::: "memory");
}
__device__ __forceinline__ void cp_wait0() {
    asm volatile("cp.async.wait_group 0;" ::: "memory");
}
__device__ __forceinline__ void cp_wait1() {
    asm volatile("cp.async.wait_group 1;" ::: "memory");
}
__device__ __forceinline__ uint32_t cvta_s(const void* p) {
    return (uint32_t)__cvta_generic_to_shared(p);
}
__device__ __forceinline__ uint32_t pack_h2(float lo, float hi) {
    __half2 h = __floats2half2_rn(lo, hi);
    return *(uint32_t*)&h;
}

// ===========================================================================
// Prep: convert x + all weights to fp16
// ===========================================================================
#define NX  (MM * EE)
#define NWQ (EE * EE)
#define NWK (KVE * EE)
#define NTOT (NX + NWQ + 2 * NWK + NWQ)

__global__ void __launch_bounds__(256)
prep_h(const float* __restrict__ x,
       const float* __restrict__ wq, const float* __restrict__ wk,
       const float* __restrict__ wv, const float* __restrict__ wo)
{
    const int nvec = NTOT / 8;
    for (int i = blockIdx.x * blockDim.x + threadIdx.x; i < nvec;
         i += gridDim.x * blockDim.x) {
        const int e = i * 8;
        const float* src;
        __half* dst;
        int off;
        if (e < NX)                    { src = x;  dst = g_xh;  off = e; }
        else if (e < NX + NWQ)         { src = wq; dst = g_wqh; off = e - NX; }
        else if (e < NX + NWQ + NWK)   { src = wk; dst = g_wkh; off = e - NX - NWQ; }
        else if (e < NX + NWQ + 2*NWK) { src = wv; dst = g_wvh; off = e - NX - NWQ - NWK; }
        else                           { src = wo; dst = g_woh; off = e - NX - NWQ - 2*NWK; }
        float4 v0 = *(const float4*)(src + off);
        float4 v1 = *(const float4*)(src + off + 4);
        __half2 h[4];
        h[0] = __floats2half2_rn(v0.x, v0.y);
        h[1] = __floats2half2_rn(v0.z, v0.w);
        h[2] = __floats2half2_rn(v1.x, v1.y);
        h[3] = __floats2half2_rn(v1.z, v1.w);
        *(uint4*)(dst + off) = *(uint4*)h;
    }
}

// ===========================================================================
// fp16 tensor-core GEMM core (m16n8k16): 128x128 CTA tile, 256 thr,
// 8 warps (2M x 4N), warp 64x32. BK=64 halves, 3-stage cp.async ring.
// OUT: 0 = fp32, 1 = fp16, 2 = fp16 transposed, 3 = fp16 * 0.125 (Q)
// ===========================================================================
#define GBK   64                       // k halves per iter
#define GROW  144                      // row stride bytes (72 halves)
#define GBUFB (128 * GROW)             // 18432 bytes per stage per operand
#define GSTG  3
#define GSMEM (2 * GSTG * GBUFB)       // 110592 bytes

template <int OUT>
__device__ __forceinline__ void gemm_core(
    const __half* __restrict__ A, const __half* __restrict__ W,
    const float* __restrict__ bias, void* __restrict__ Cv,
    int Nc, int row0)
{
    extern __shared__ char smraw[];
    const uint32_t sbase = cvta_s(smraw);

    const int tid = threadIdx.x;

    // staging: 2 threads per row, 32 halves (64 B = 4 cp16) each
    const int r   = tid >> 1;
    const int seg = (tid & 1) * 32;
    const __half* Ag = A + (size_t)(row0 + r) * EE + seg;
    const __half* Wg = W + (size_t)r * EE + seg;
    const uint32_t Asd = sbase + r * GROW + seg * 2;
    const uint32_t Bsd = sbase + GSTG * GBUFB + r * GROW + seg * 2;

    const int lane = tid & 31;
    const int wid  = tid >> 5;
    const int wm   = (wid & 1) * 64;
    const int wn   = (wid >> 1) * 32;
    const int g    = lane >> 2;
    const int tig  = lane & 3;

    const uint32_t aoff = (wm + (lane & 15)) * GROW + ((lane & 16) ? 16 : 0);
    const uint32_t boff = (wn + (lane & 15)) * GROW + ((lane & 16) ? 16 : 0);

    float acc[4][4][4];
#pragma unroll
    for (int mt = 0; mt < 4; mt++)
#pragma unroll
        for (int nt = 0; nt < 4; nt++)
#pragma unroll
            for (int i = 0; i < 4; i++) acc[mt][nt][i] = 0.f;

    // prologue: stage k-chunks 0 and 1
#pragma unroll
    for (int s = 0; s < 2; s++) {
#pragma unroll
        for (int i = 0; i < 4; i++) {
            cp16(Asd + s * GBUFB + i * 16, Ag + s * GBK + i * 8);
            cp16(Bsd + s * GBUFB + i * 16, Wg + s * GBK + i * 8);
        }
        cp_commit();
    }

    const int NI = EE / GBK;           // 16
    int bcur = 0, bpre = 2;
    for (int it = 0; it < NI; it++) {
        if (it + 1 < NI) cp_wait1(); else cp_wait0();
        __syncthreads();

        if (it + 2 < NI) {
            const __half* a = Ag + (it + 2) * GBK;
            const __half* w = Wg + (it + 2) * GBK;
            const uint32_t ad = Asd + bpre * GBUFB;
            const uint32_t bd = Bsd + bpre * GBUFB;
#pragma unroll
            for (int i = 0; i < 4; i++) {
                cp16(ad + i * 16, a + i * 8);
                cp16(bd + i * 16, w + i * 8);
            }
            cp_commit();
        }

        const uint32_t Ab = sbase + bcur * GBUFB + aoff;
        const uint32_t Bb = sbase + GSTG * GBUFB + bcur * GBUFB + boff;
#pragma unroll
        for (int ks = 0; ks < 4; ks++) {       // 4 k16-steps per iter
            uint32_t a[4][4], b[2][4];
#pragma unroll
            for (int mt = 0; mt < 4; mt++)
                ldsm_x4(a[mt], Ab + mt * 16 * GROW + ks * 32);
#pragma unroll
            for (int np = 0; np < 2; np++)
                ldsm_x4(b[np], Bb + np * 16 * GROW + ks * 32);
#pragma unroll
            for (int mt = 0; mt < 4; mt++)
#pragma unroll
                for (int np = 0; np < 2; np++) {
                    mma_f16(acc[mt][2*np],   a[mt], b[np][0], b[np][2]);
                    mma_f16(acc[mt][2*np+1], a[mt], b[np][1], b[np][3]);
                }
        }

        bcur = (bcur + 1 == GSTG) ? 0 : bcur + 1;
        bpre = (bpre + 1 == GSTG) ? 0 : bpre + 1;
    }

#pragma unroll
    for (int mt = 0; mt < 4; mt++) {
        const int rowa = row0 + wm + mt * 16 + g;
#pragma unroll
        for (int nt = 0; nt < 4; nt++) {
            const int cola = wn + nt * 8 + 2 * tig;
            const float2 bv = *(const float2*)(bias + cola);
            float s0 = acc[mt][nt][0] + bv.x;
            float s1 = acc[mt][nt][1] + bv.y;
            float s2 = acc[mt][nt][2] + bv.x;
            float s3 = acc[mt][nt][3] + bv.y;
            if (OUT == 0) {
                float* C = (float*)Cv;
                *(float2*)(C + (size_t)rowa * Nc + cola)       = make_float2(s0, s1);
                *(float2*)(C + (size_t)(rowa + 8) * Nc + cola) = make_float2(s2, s3);
            } else if (OUT == 2) {     // transposed fp16: C[col * MM + row]
                __half* C = (__half*)Cv;
                C[(size_t)cola * MM + rowa]           = __float2half_rn(s0);
                C[(size_t)(cola + 1) * MM + rowa]     = __float2half_rn(s1);
                C[(size_t)cola * MM + rowa + 8]       = __float2half_rn(s2);
                C[(size_t)(cola + 1) * MM + rowa + 8] = __float2half_rn(s3);
            } else {
                const float sc = (OUT == 3) ? 0.125f : 1.f;   // exact pow2
                __half* C = (__half*)Cv;
                __half2 v0 = __floats2half2_rn(s0 * sc, s1 * sc);
                __half2 v1 = __floats2half2_rn(s2 * sc, s3 * sc);
                *(__half2*)(C + (size_t)rowa * Nc + cola)       = v0;
                *(__half2*)(C + (size_t)(rowa + 8) * Nc + cola) = v1;
            }
        }
    }
}

// fused Q/K/V projection: tiles 0-7 -> Q(x0.125), 8-9 -> K, 10-11 -> V(transposed)
__global__ void __launch_bounds__(256, 2)
gemm_qkv(const float* __restrict__ bq, const float* __restrict__ bk,
         const float* __restrict__ bv)
{
    const int bx   = blockIdx.x;
    const int row0 = blockIdx.y * 128;
    if (bx < 8) {
        const int c0 = bx * 128;
        gemm_core<3>(g_xh, g_wqh + (size_t)c0 * EE, bq + c0, g_Qh + c0, EE, row0);
    } else if (bx < 10) {
        const int c0 = (bx - 8) * 128;
        gemm_core<1>(g_xh, g_wkh + (size_t)c0 * EE, bk + c0, g_Kh + c0, KVE, row0);
    } else {
        const int c0 = (bx - 10) * 128;
        gemm_core<2>(g_xh, g_wvh + (size_t)c0 * EE, bv + c0,
                     g_Vth + (size_t)c0 * MM, KVE, row0);
    }
}

__global__ void __launch_bounds__(256, 2)
gemm_single(const float* __restrict__ bias, float* __restrict__ C)
{
    const int c0 = blockIdx.x * 128;
    gemm_core<0>(g_Ch, g_woh + (size_t)c0 * EE, bias + c0, C + c0, EE,
                 blockIdx.y * 128);
}

// ===========================================================================
// fp16 tensor-core flash attention (causal, GQA), m16n8k16.
// Q frags in regs; K smem [kv][d]; V smem [d][kv]; P entirely in registers
// (C-fragment -> A-fragment layout match). 2-stage cp.async K/V ring.
// ===========================================================================
#define FROW  144                     // row stride bytes (72 halves)
#define FQB   (128 * FROW)            // 18432
#define FKB   (64 * FROW)             // 9216
#define FSMEM (FQB + 4 * FKB)         // 55296 bytes

__global__ void __launch_bounds__(256, 2)
flash_tc(float* __restrict__ dummy)   // unused; globals accessed directly
{
    extern __shared__ char smraw[];
    const uint32_t sbase = cvta_s(smraw);

    const int tid  = threadIdx.x;
    const int lane = tid & 31;
    const int wid  = tid >> 5;
    const int g    = lane >> 2;
    const int tig  = lane & 3;
    const int m0   = (gridDim.x - 1 - blockIdx.x) * 128;   // heavy-first
    const int h    = blockIdx.y;
    const int b    = blockIdx.z;
    const int kvh  = h >> 2;

    // K/V staging: 4 threads per row, 16 halves (32 B = 2 cp16) each
    const int sr  = tid >> 2;          // 0..63
    const int sck = (tid & 3) * 16;
    const __half* kgb = g_Kh + ((size_t)(b * SS + sr)) * KVE + kvh * DD + sck;
    const __half* vgb = g_Vth + ((size_t)(kvh * DD + sr)) * MM + b * SS + sck;
    const uint32_t kd0 = sbase + FQB + sr * FROW + sck * 2;
    const uint32_t vd0 = sbase + FQB + 2 * FKB + sr * FROW + sck * 2;

    // fragment lane offsets
    const uint32_t qoff = (wid * 16 + (lane & 15)) * FROW + ((lane & 16) ? 16 : 0);
    const uint32_t kvoff = (lane & 15) * FROW + ((lane & 16) ? 16 : 0);

    // stage Q (already 1/8-scaled fp16): 2 threads/row, 4 cp16 each
    {
        const int rq   = tid >> 1;
        const int segq = (tid & 1) * 32;
        const __half* qg = g_Qh + ((size_t)(b * SS + m0 + rq)) * EE + h * DD + segq;
        const uint32_t qd = sbase + rq * FROW + segq * 2;
#pragma unroll
        for (int i = 0; i < 4; i++) cp16(qd + i * 16, qg + i * 8);
    }
    // stage KV tile 0 into buffer 0
#pragma unroll
    for (int i = 0; i < 2; i++) {
        cp16(kd0 + i * 16, kgb + i * 8);
        cp16(vd0 + i * 16, vgb + i * 8);
    }
    cp_commit();
    cp_wait0();
    __syncthreads();

    // Q A-fragments (4 k16-steps over d=64)
    uint32_t qa[4][4];
#pragma unroll
    for (int ks = 0; ks < 4; ks++)
        ldsm_x4(qa[ks], sbase + qoff + ks * 32);

    float oacc[8][4];
#pragma unroll
    for (int nt = 0; nt < 8; nt++)
#pragma unroll
        for (int i = 0; i < 4; i++) oacc[nt][i] = 0.f;
    float mrow[2] = { -1e30f, -1e30f };
    float lrow[2] = { 0.f, 0.f };

    const int r0 = m0 + wid * 16 + g;
    const int ntile = m0 / 64 + 2;

    for (int t = 0; t < ntile; t++) {
        const int cb = t & 1;

        if (t > 0) {                   // tile-t data already waited at t=0
            cp_wait0();
            __syncthreads();
        }

        if (t + 1 < ntile) {           // prefetch next tile (buffer safe post-sync)
            const __half* kg = kgb + (size_t)((t + 1) * 64) * KVE;
            const __half* vg = vgb + (t + 1) * 64;
            const uint32_t kd = kd0 + (1 - cb) * FKB;
            const uint32_t vd = vd0 + (1 - cb) * FKB;
#pragma unroll
            for (int i = 0; i < 2; i++) {
                cp16(kd + i * 16, kg + i * 8);
                cp16(vd + i * 16, vg + i * 8);
            }
            cp_commit();
        }

        const int j0 = t * 64;
        const bool active = (j0 <= m0 + wid * 16 + 15);    // warp-uniform
        if (active) {
            const uint32_t Kc = sbase + FQB + cb * FKB + kvoff;
            const uint32_t Vc = sbase + FQB + 2 * FKB + cb * FKB + kvoff;

            // S = Q @ K^T   (B from K [n=kv][k=d])
            float sc[8][4];
#pragma unroll
            for (int nt = 0; nt < 8; nt++)
#pragma unroll
                for (int i = 0; i < 4; i++) sc[nt][i] = 0.f;
#pragma unroll
            for (int ks = 0; ks < 4; ks++) {
#pragma unroll
                for (int np = 0; np < 4; np++) {
                    uint32_t kb[4];
                    ldsm_x4(kb, Kc + np * 16 * FROW + ks * 32);
                    mma_f16(sc[2*np],   qa[ks], kb[0], kb[2]);
                    mma_f16(sc[2*np+1], qa[ks], kb[1], kb[3]);
                }
            }

            // causal mask (diagonal tiles only)
            if (j0 + 63 > r0) {
#pragma unroll
                for (int nt = 0; nt < 8; nt++) {
                    const int c = j0 + nt * 8 + 2 * tig;
                    if (c     > r0)     sc[nt][0] = -1e30f;
                    if (c + 1 > r0)     sc[nt][1] = -1e30f;
                    if (c     > r0 + 8) sc[nt][2] = -1e30f;
                    if (c + 1 > r0 + 8) sc[nt][3] = -1e30f;
                }
            }

            // row max (quad reduce)
            float tm0 = -1e30f, tm1 = -1e30f;
#pragma unroll
            for (int nt = 0; nt < 8; nt++) {
                tm0 = fmaxf(tm0, fmaxf(sc[nt][0], sc[nt][1]));
                tm1 = fmaxf(tm1, fmaxf(sc[nt][2], sc[nt][3]));
            }
            tm0 = fmaxf(tm0, __shfl_xor_sync(0xffffffffu, tm0, 1));
            tm0 = fmaxf(tm0, __shfl_xor_sync(0xffffffffu, tm0, 2));
            tm1 = fmaxf(tm1, __shfl_xor_sync(0xffffffffu, tm1, 1));
            tm1 = fmaxf(tm1, __shfl_xor_sync(0xffffffffu, tm1, 2));

            const float mn0 = fmaxf(mrow[0], tm0);
            const float mn1 = fmaxf(mrow[1], tm1);
            const float cr0 = __expf(mrow[0] - mn0);
            const float cr1 = __expf(mrow[1] - mn1);
            mrow[0] = mn0; mrow[1] = mn1;

            float ls0 = 0.f, ls1 = 0.f;
#pragma unroll
            for (int nt = 0; nt < 8; nt++) {
                sc[nt][0] = __expf(sc[nt][0] - mn0); ls0 += sc[nt][0];
                sc[nt][1] = __expf(sc[nt][1] - mn0); ls0 += sc[nt][1];
                sc[nt][2] = __expf(sc[nt][2] - mn1); ls1 += sc[nt][2];
                sc[nt][3] = __expf(sc[nt][3] - mn1); ls1 += sc[nt][3];
            }
            lrow[0] = lrow[0] * cr0 + ls0;
            lrow[1] = lrow[1] * cr1 + ls1;
#pragma unroll
            for (int nt = 0; nt < 8; nt++) {
                oacc[nt][0] *= cr0; oacc[nt][1] *= cr0;
                oacc[nt][2] *= cr1; oacc[nt][3] *= cr1;
            }

            // O += P @ V — P converted in-register (C-frag == A-frag for f16)
#pragma unroll
            for (int ks = 0; ks < 4; ks++) {   // kv chunks of 16
                uint32_t pa[4];
                pa[0] = pack_h2(sc[2*ks][0],   sc[2*ks][1]);
                pa[1] = pack_h2(sc[2*ks][2],   sc[2*ks][3]);
                pa[2] = pack_h2(sc[2*ks+1][0], sc[2*ks+1][1]);
                pa[3] = pack_h2(sc[2*ks+1][2], sc[2*ks+1][3]);
#pragma unroll
                for (int np = 0; np < 4; np++) {
                    uint32_t vb[4];
                    ldsm_x4(vb, Vc + np * 16 * FROW + ks * 32);
                    mma_f16(oacc[2*np],   pa, vb[0], vb[2]);
                    mma_f16(oacc[2*np+1], pa, vb[1], vb[3]);
                }
            }
        }
    }

    // finalize: quad-reduce l, normalize, store context fp16
    lrow[0] += __shfl_xor_sync(0xffffffffu, lrow[0], 1);
    lrow[0] += __shfl_xor_sync(0xffffffffu, lrow[0], 2);
    lrow[1] += __shfl_xor_sync(0xffffffffu, lrow[1], 1);
    lrow[1] += __shfl_xor_sync(0xffffffffu, lrow[1], 2);
    const float inv0 = 1.f / lrow[0];
    const float inv1 = 1.f / lrow[1];

    __half* og = g_Ch + ((size_t)(b * SS + r0)) * EE + h * DD;
#pragma unroll
    for (int nt = 0; nt < 8; nt++) {
        __half2 v0 = __floats2half2_rn(oacc[nt][0] * inv0, oacc[nt][1] * inv0);
        __half2 v1 = __floats2half2_rn(oacc[nt][2] * inv1, oacc[nt][3] * inv1);
        *(__half2*)(og + nt * 8 + 2 * tig)                  = v0;
        *(__half2*)(og + (size_t)8 * EE + nt * 8 + 2 * tig) = v1;
    }
}

// ---------------------------------------------------------------------------
// Launch
// ---------------------------------------------------------------------------
extern "C" void kernel_launch(void* const* d_in, const int* in_sizes, int n_in,
                              void* d_out, int out_size)
{
    const float* x    = (const float*)d_in[0];
    // d_in[1] is the causal mask (triu, k=1) — applied analytically (j<=i).
    const float* wq_w = (const float*)d_in[2];
    const float* wq_b = (const float*)d_in[3];
    const float* wk_w = (const float*)d_in[4];
    const float* wk_b = (const float*)d_in[5];
    const float* wv_w = (const float*)d_in[6];
    const float* wv_b = (const float*)d_in[7];
    const float* wo_w = (const float*)d_in[8];
    const float* wo_b = (const float*)d_in[9];
    float* out = (float*)d_out;

    cudaFuncSetAttribute(gemm_qkv,
                         cudaFuncAttributeMaxDynamicSharedMemorySize, GSMEM);
    cudaFuncSetAttribute(gemm_single,
                         cudaFuncAttributeMaxDynamicSharedMemorySize, GSMEM);
    cudaFuncSetAttribute(flash_tc,
                         cudaFuncAttributeMaxDynamicSharedMemorySize, FSMEM);

    // convert x + weights to fp16
    prep_h<<<1024, 256>>>(x, wq_w, wk_w, wv_w, wo_w);

    // fused Q/K/V projections (Q pre-scaled, V transposed)
    gemm_qkv<<<dim3(12, MM / 128), 256, GSMEM>>>(wq_b, wk_b, wv_b);

    // causal GQA flash attention
    flash_tc<<<dim3(SS / 128, HH, BB), 256, FSMEM>>>(out);

    // output projection (fp32 out)
    gemm_single<<<dim3(EE / 128, MM / 128), 256, GSMEM>>>(wo_b, out);
}